// round 1
// baseline (speedup 1.0000x reference)
#include <cuda_runtime.h>
#include <math.h>

#define Bb 64
#define Ff 256
#define Tt 1024
#define Hh 1024
#define Oo 512
#define RNCTA 128
#define NT 8

// Scratch (device-global: no allocations allowed)
__device__ float g_xT[(size_t)Tt * Bb * Ff];      // x transposed to (T, B, F)
__device__ float g_U [(size_t)Tt * Bb * Hh];      // U = x@Wx + b, overwritten in-place with states
__device__ float g_WhT[(size_t)Hh * Hh];          // Wh transposed (WhT[n][k] = Wh[k][n])
__device__ float g_S[2][Bb * Hh];                 // double-buffered recurrent state
__device__ unsigned int g_cnt;                    // grid barrier (zero-init, restored each run)
__device__ unsigned int g_sense;

__device__ __forceinline__ float ftanh(float x) {
    float xc = fminf(fmaxf(x, -15.0f), 15.0f);
    float e  = __expf(2.0f * xc);
    return __fdividef(e - 1.0f, e + 1.0f);
}

// Sense-reversing software grid barrier. All RNCTA CTAs are co-resident
// (single wave: 128 CTAs <= 148 SMs, 1 CTA/SM). After an even number of
// barriers, {g_cnt, g_sense} return to {0,0} -> safe across graph replays.
__device__ __forceinline__ void gridbar(unsigned s) {
    __syncthreads();
    if (threadIdx.x == 0) {
        __threadfence();
        unsigned prev = atomicAdd(&g_cnt, 1u);
        if (prev == RNCTA - 1) {
            atomicExch(&g_cnt, 0u);
            __threadfence();
            atomicExch(&g_sense, s);
        } else {
            while (*((volatile unsigned int*)&g_sense) != s) { }
        }
        __threadfence();
    }
    __syncthreads();
}

// x (B,F,T) -> g_xT (T,B,F)
__global__ void transpose_x_kernel(const float* __restrict__ x) {
    __shared__ float tile[32][33];
    int b  = blockIdx.z;
    int t0 = blockIdx.x * 32;
    int f0 = blockIdx.y * 32;
    const float* xb = x + (size_t)b * Ff * Tt;
    for (int i = threadIdx.y; i < 32; i += 8)
        tile[i][threadIdx.x] = xb[(size_t)(f0 + i) * Tt + t0 + threadIdx.x];
    __syncthreads();
    for (int i = threadIdx.y; i < 32; i += 8)
        g_xT[((size_t)(t0 + i) * Bb + b) * Ff + f0 + threadIdx.x] = tile[threadIdx.x][i];
}

// Wh (H,H) -> g_WhT (WhT[n][k] = Wh[k][n])
__global__ void transpose_wh_kernel(const float* __restrict__ Wh) {
    __shared__ float tile[32][33];
    int k0 = blockIdx.x * 32;
    int n0 = blockIdx.y * 32;
    for (int i = threadIdx.y; i < 32; i += 8)
        tile[i][threadIdx.x] = Wh[(size_t)(k0 + i) * Hh + n0 + threadIdx.x];
    __syncthreads();
    for (int i = threadIdx.y; i < 32; i += 8)
        g_WhT[(size_t)(n0 + i) * Hh + k0 + threadIdx.x] = tile[threadIdx.x][i];
}

// U[t][b][h] = bias[h] + sum_f xT[t][b][f] * Wx[f][h]
// CTA tile: 64(b) x 64(h), K=F=256, 4x4 micro-tile, register-prefetch pipeline.
__global__ __launch_bounds__(256) void u_gemm_kernel(const float* __restrict__ Wx,
                                                     const float* __restrict__ bias) {
    const int t  = blockIdx.y;
    const int h0 = blockIdx.x * 64;
    __shared__ float As[16][68];
    __shared__ float Bs[16][68];
    const int tid = threadIdx.x;
    const int tx = tid & 15, ty = tid >> 4;
    const int am = tid >> 2, ak = (tid & 3) * 4;
    const int bk = tid >> 4, bn = (tid & 15) * 4;
    const float* A = g_xT + (size_t)t * Bb * Ff;

    float acc[4][4] = {};
    float4 ra = *(const float4*)(A + (size_t)am * Ff + ak);
    float4 rb = *(const float4*)(Wx + (size_t)bk * Hh + h0 + bn);

    for (int k0 = 0; k0 < Ff; k0 += 16) {
        As[ak + 0][am] = ra.x; As[ak + 1][am] = ra.y;
        As[ak + 2][am] = ra.z; As[ak + 3][am] = ra.w;
        *(float4*)&Bs[bk][bn] = rb;
        __syncthreads();
        if (k0 + 16 < Ff) {
            ra = *(const float4*)(A + (size_t)am * Ff + k0 + 16 + ak);
            rb = *(const float4*)(Wx + (size_t)(k0 + 16 + bk) * Hh + h0 + bn);
        }
        #pragma unroll
        for (int kk = 0; kk < 16; ++kk) {
            float4 a = *(const float4*)&As[kk][4 * ty];
            float4 b = *(const float4*)&Bs[kk][4 * tx];
            float av[4] = {a.x, a.y, a.z, a.w};
            float bv[4] = {b.x, b.y, b.z, b.w};
            #pragma unroll
            for (int i = 0; i < 4; ++i)
                #pragma unroll
                for (int j = 0; j < 4; ++j)
                    acc[i][j] = fmaf(av[i], bv[j], acc[i][j]);
        }
        __syncthreads();
    }
    float4 bv4 = *(const float4*)(bias + h0 + 4 * tx);
    #pragma unroll
    for (int i = 0; i < 4; ++i) {
        float4 v = make_float4(acc[i][0] + bv4.x, acc[i][1] + bv4.y,
                               acc[i][2] + bv4.z, acc[i][3] + bv4.w);
        *(float4*)&g_U[((size_t)t * Bb + 4 * ty + i) * Hh + h0 + 4 * tx] = v;
    }
}

// Persistent recurrence: 128 CTAs, CTA owns 8 hidden columns; 8 warps split K.
// S_t = tanh(U_t + S_{t-1} @ Wh); states written in-place over g_U.
__global__ __launch_bounds__(256, 1) void rnn_kernel() {
    const int n0   = blockIdx.x * NT;
    const int w    = threadIdx.x >> 5;
    const int lane = threadIdx.x & 31;
    const int k0   = w * 128;
    __shared__ float red[8][512];   // [warp][b*8 + c]

    // t = 0: state = tanh(U[0])
    if (threadIdx.x < 128) {
        int j = threadIdx.x * 4;
        int b = j >> 3, c4 = j & 7;
        size_t ui = (size_t)b * Hh + n0 + c4;
        float4 u = *(const float4*)&g_U[ui];
        float4 st = make_float4(ftanh(u.x), ftanh(u.y), ftanh(u.z), ftanh(u.w));
        *(float4*)&g_U[ui] = st;
        *(float4*)&g_S[0][(size_t)b * Hh + n0 + c4] = st;
    }
    gridbar(1u);

    for (int t = 1; t < Tt; ++t) {
        const float* Sp = g_S[(t + 1) & 1];
        float*       Sn = g_S[t & 1];

        float acc[2][8];
        #pragma unroll
        for (int i = 0; i < 2; ++i)
            #pragma unroll
            for (int c = 0; c < 8; ++c) acc[i][c] = 0.0f;

        const float4* s0p = (const float4*)(Sp + (size_t)lane * Hh + k0);
        const float4* s1p = (const float4*)(Sp + (size_t)(lane + 32) * Hh + k0);

        #pragma unroll 2
        for (int kq = 0; kq < 32; ++kq) {
            float4 s0 = __ldcg(s0p + kq);   // bypass L1: S changes every step
            float4 s1 = __ldcg(s1p + kq);
            #pragma unroll
            for (int cc = 0; cc < 8; ++cc) {
                float4 wv = *(const float4*)(g_WhT + (size_t)(n0 + cc) * Hh + k0 + 4 * kq);
                acc[0][cc] = fmaf(s0.x, wv.x, fmaf(s0.y, wv.y,
                             fmaf(s0.z, wv.z, fmaf(s0.w, wv.w, acc[0][cc]))));
                acc[1][cc] = fmaf(s1.x, wv.x, fmaf(s1.y, wv.y,
                             fmaf(s1.z, wv.z, fmaf(s1.w, wv.w, acc[1][cc]))));
            }
        }

        *(float4*)&red[w][lane * 8]            = make_float4(acc[0][0], acc[0][1], acc[0][2], acc[0][3]);
        *(float4*)&red[w][lane * 8 + 4]        = make_float4(acc[0][4], acc[0][5], acc[0][6], acc[0][7]);
        *(float4*)&red[w][(lane + 32) * 8]     = make_float4(acc[1][0], acc[1][1], acc[1][2], acc[1][3]);
        *(float4*)&red[w][(lane + 32) * 8 + 4] = make_float4(acc[1][4], acc[1][5], acc[1][6], acc[1][7]);
        __syncthreads();

        if (threadIdx.x < 128) {
            int j = threadIdx.x * 4;
            float4 sum = *(const float4*)&red[0][j];
            #pragma unroll
            for (int ww = 1; ww < 8; ++ww) {
                float4 r = *(const float4*)&red[ww][j];
                sum.x += r.x; sum.y += r.y; sum.z += r.z; sum.w += r.w;
            }
            int b = j >> 3, c4 = j & 7;
            size_t ui = ((size_t)t * Bb + b) * Hh + n0 + c4;
            float4 u = *(const float4*)&g_U[ui];
            float4 st = make_float4(ftanh(u.x + sum.x), ftanh(u.y + sum.y),
                                    ftanh(u.z + sum.z), ftanh(u.w + sum.w));
            *(float4*)&g_U[ui] = st;                              // store state for out-GEMM
            *(float4*)&Sn[(size_t)b * Hh + n0 + c4] = st;         // next-step input
        }
        gridbar((unsigned)((t & 1) ^ 1));
    }
}

// out[b][t][o] = bout[o] + sum_h states[t][b][h] * Wout[h][o]
__global__ __launch_bounds__(256) void out_gemm_kernel(const float* __restrict__ Wout,
                                                       const float* __restrict__ bout,
                                                       float* __restrict__ out) {
    const int t  = blockIdx.y;
    const int o0 = blockIdx.x * 64;
    __shared__ float As[16][68];
    __shared__ float Bs[16][68];
    const int tid = threadIdx.x;
    const int tx = tid & 15, ty = tid >> 4;
    const int am = tid >> 2, ak = (tid & 3) * 4;
    const int bk = tid >> 4, bn = (tid & 15) * 4;
    const float* A = g_U + (size_t)t * Bb * Hh;

    float acc[4][4] = {};
    float4 ra = *(const float4*)(A + (size_t)am * Hh + ak);
    float4 rb = *(const float4*)(Wout + (size_t)bk * Oo + o0 + bn);

    for (int k0 = 0; k0 < Hh; k0 += 16) {
        As[ak + 0][am] = ra.x; As[ak + 1][am] = ra.y;
        As[ak + 2][am] = ra.z; As[ak + 3][am] = ra.w;
        *(float4*)&Bs[bk][bn] = rb;
        __syncthreads();
        if (k0 + 16 < Hh) {
            ra = *(const float4*)(A + (size_t)am * Hh + k0 + 16 + ak);
            rb = *(const float4*)(Wout + (size_t)(k0 + 16 + bk) * Oo + o0 + bn);
        }
        #pragma unroll
        for (int kk = 0; kk < 16; ++kk) {
            float4 a = *(const float4*)&As[kk][4 * ty];
            float4 b = *(const float4*)&Bs[kk][4 * tx];
            float av[4] = {a.x, a.y, a.z, a.w};
            float bv[4] = {b.x, b.y, b.z, b.w};
            #pragma unroll
            for (int i = 0; i < 4; ++i)
                #pragma unroll
                for (int j = 0; j < 4; ++j)
                    acc[i][j] = fmaf(av[i], bv[j], acc[i][j]);
        }
        __syncthreads();
    }
    float4 bo = *(const float4*)(bout + o0 + 4 * tx);
    #pragma unroll
    for (int i = 0; i < 4; ++i) {
        float4 v = make_float4(acc[i][0] + bo.x, acc[i][1] + bo.y,
                               acc[i][2] + bo.z, acc[i][3] + bo.w);
        *(float4*)&out[((size_t)(4 * ty + i) * Tt + t) * Oo + o0 + 4 * tx] = v;
    }
}

extern "C" void kernel_launch(void* const* d_in, const int* in_sizes, int n_in,
                              void* d_out, int out_size) {
    const float* x    = (const float*)d_in[0];
    const float* Wx   = (const float*)d_in[1];
    const float* Wh   = (const float*)d_in[2];
    const float* bias = (const float*)d_in[3];
    const float* Wout = (const float*)d_in[4];
    const float* bout = (const float*)d_in[5];
    float* out = (float*)d_out;

    transpose_x_kernel <<<dim3(Tt / 32, Ff / 32, Bb), dim3(32, 8)>>>(x);
    transpose_wh_kernel<<<dim3(Hh / 32, Hh / 32),     dim3(32, 8)>>>(Wh);
    u_gemm_kernel      <<<dim3(Hh / 64, Tt), 256>>>(Wx, bias);
    rnn_kernel         <<<RNCTA, 256>>>();
    out_gemm_kernel    <<<dim3(Oo / 64, Tt), 256>>>(Wout, bout, out);
}

// round 2
// speedup vs baseline: 1.3697x; 1.3697x over previous
#include <cuda_runtime.h>
#include <math.h>

#define Bb 64
#define Ff 256
#define Tt 1024
#define Hh 1024
#define Oo 512
#define RNCTA 128

typedef unsigned long long ull;

// Scratch (device globals: no allocations allowed)
__device__ float g_xT[(size_t)Tt * Bb * Ff];        // x transposed to (T, B, F)
__device__ float g_U [(size_t)Tt * Hh * Bb];        // U/states, layout [t][h][b] (b contiguous)
__device__ float g_S[2][Hh * Bb];                   // recurrent state, [h][b]
__device__ unsigned int g_cnt;                      // grid barrier (returns to {0,0} each run)
__device__ unsigned int g_sense;

// ---------- packed f32x2 helpers (Blackwell: 2x fp32 FMA throughput) ----------
__device__ __forceinline__ ull pk2(float lo, float hi) {
    ull r; asm("mov.b64 %0, {%1, %2};" : "=l"(r) : "f"(lo), "f"(hi)); return r;
}
__device__ __forceinline__ ull ffma2(ull a, ull b, ull c) {
    ull d; asm("fma.rn.f32x2 %0, %1, %2, %3;" : "=l"(d) : "l"(a), "l"(b), "l"(c)); return d;
}
__device__ __forceinline__ ull addf2(ull a, ull b) {
    ull d; asm("add.rn.f32x2 %0, %1, %2;" : "=l"(d) : "l"(a), "l"(b)); return d;
}
__device__ __forceinline__ float2 upk2(ull v) {
    float2 f; asm("mov.b64 {%0, %1}, %2;" : "=f"(f.x), "=f"(f.y) : "l"(v)); return f;
}

__device__ __forceinline__ float ftanh(float x) {
    float xc = fminf(fmaxf(x, -15.0f), 15.0f);
    float e  = __expf(2.0f * xc);
    return __fdividef(e - 1.0f, e + 1.0f);
}

// Sense-reversing software grid barrier; all RNCTA CTAs co-resident in wave 1.
__device__ __forceinline__ void gridbar(unsigned s) {
    __syncthreads();
    if (threadIdx.x == 0) {
        __threadfence();
        unsigned prev = atomicAdd(&g_cnt, 1u);
        if (prev == RNCTA - 1) {
            atomicExch(&g_cnt, 0u);
            __threadfence();
            atomicExch(&g_sense, s);
        } else {
            while (*((volatile unsigned int*)&g_sense) != s) { }
        }
        __threadfence();
    }
    __syncthreads();
}

// x (B,F,T) -> g_xT (T,B,F)
__global__ void transpose_x_kernel(const float* __restrict__ x) {
    __shared__ float tile[32][33];
    int b  = blockIdx.z;
    int t0 = blockIdx.x * 32;
    int f0 = blockIdx.y * 32;
    const float* xb = x + (size_t)b * Ff * Tt;
    for (int i = threadIdx.y; i < 32; i += 8)
        tile[i][threadIdx.x] = xb[(size_t)(f0 + i) * Tt + t0 + threadIdx.x];
    __syncthreads();
    for (int i = threadIdx.y; i < 32; i += 8)
        g_xT[((size_t)(t0 + i) * Bb + b) * Ff + f0 + threadIdx.x] = tile[threadIdx.x][i];
}

// U[t][h][b] = bias[h] + sum_f xT[t][b][f] * Wx[f][h]
// CTA: 64h x 64b tile for one t. A = Wx (k=f major, h contig) -> direct smem.
// B = xT slice, transposed into smem [f][b]. acc packed along b via f32x2.
__global__ __launch_bounds__(256) void u_gemm_kernel(const float* __restrict__ Wx,
                                                     const float* __restrict__ bias) {
    const int t  = blockIdx.y;
    const int h0 = blockIdx.x * 64;
    __shared__ __align__(16) float As[16][68];   // [k][h]
    __shared__ __align__(16) float Bs[16][68];   // [k][b]
    const int tid = threadIdx.x;
    const int tx = tid & 15, ty = tid >> 4;      // tx -> b (4), ty -> h (4)
    const int ar = tid >> 4, ac = (tid & 15) * 4;   // A load: row k, 4 h
    const int bb = tid >> 2, bf = (tid & 3) * 4;    // B load: b row, 4 f
    const float* Xr = g_xT + ((size_t)t * Bb + bb) * Ff;

    ull acc[4][2];
    #pragma unroll
    for (int i = 0; i < 4; ++i) { acc[i][0] = 0ull; acc[i][1] = 0ull; }

    float4 ra = *(const float4*)(Wx + (size_t)ar * Hh + h0 + ac);
    float4 rb = *(const float4*)(Xr + bf);

    for (int k0 = 0; k0 < Ff; k0 += 16) {
        *(float4*)&As[ar][ac] = ra;
        Bs[bf + 0][bb] = rb.x; Bs[bf + 1][bb] = rb.y;
        Bs[bf + 2][bb] = rb.z; Bs[bf + 3][bb] = rb.w;
        __syncthreads();
        if (k0 + 16 < Ff) {
            ra = *(const float4*)(Wx + (size_t)(k0 + 16 + ar) * Hh + h0 + ac);
            rb = *(const float4*)(Xr + k0 + 16 + bf);
        }
        #pragma unroll
        for (int kk = 0; kk < 16; ++kk) {
            float4 a = *(const float4*)&As[kk][4 * ty];
            ulonglong2 b2 = *(const ulonglong2*)&Bs[kk][4 * tx];
            float av[4] = {a.x, a.y, a.z, a.w};
            #pragma unroll
            for (int i = 0; i < 4; ++i) {
                ull sp = pk2(av[i], av[i]);
                acc[i][0] = ffma2(sp, b2.x, acc[i][0]);
                acc[i][1] = ffma2(sp, b2.y, acc[i][1]);
            }
        }
        __syncthreads();
    }
    #pragma unroll
    for (int i = 0; i < 4; ++i) {
        float bv = bias[h0 + 4 * ty + i];
        float2 lo = upk2(acc[i][0]), hi = upk2(acc[i][1]);
        float4 v = make_float4(lo.x + bv, lo.y + bv, hi.x + bv, hi.y + bv);
        *(float4*)&g_U[((size_t)t * Hh + h0 + 4 * ty + i) * Bb + 4 * tx] = v;
    }
}

// Persistent recurrence. 128 CTAs; CTA owns 8 hidden cols (n0..n0+7).
// Wh rows for those cols staged in SMEM once. 8 warps split K (128 each).
// S layout [k][b]: warp lane loads float2 at ST[k][2*lane] -> fully coalesced.
// acc packed along n (f32x2): W pairs come straight from SMEM as ulonglong2.
__global__ __launch_bounds__(256, 1) void rnn_kernel(const float* __restrict__ Wh) {
    const int n0   = blockIdx.x * 8;
    const int tid  = threadIdx.x;
    const int w    = tid >> 5;
    const int lane = tid & 31;
    const int k0   = w * 128;

    __shared__ __align__(16) float Ws[Hh * 8];          // [k][8] = 32 KB
    __shared__ __align__(16) ull   red2[8][256];        // [warp][npair*64 + b] = 16 KB

    // Stage Wh[k][n0..n0+7] -> Ws[k*8..]
    for (int q = tid; q < 2048; q += 256) {             // q indexes float4s
        int k = q >> 1, half = (q & 1) * 4;
        *(float4*)&Ws[k * 8 + half] =
            *(const float4*)&Wh[(size_t)k * Hh + n0 + half];
    }

    // t = 0: state = tanh(U[0])
    if (tid < 128) {
        int p = tid >> 5, m = tid & 31;                 // npair p, b-pair base 2m
        #pragma unroll
        for (int e = 0; e < 2; ++e) {
            int h = n0 + 2 * p + e;
            size_t ui = (size_t)h * Bb + 2 * m;
            float2 u = *(const float2*)&g_U[ui];
            float2 st = make_float2(ftanh(u.x), ftanh(u.y));
            *(float2*)&g_U[ui] = st;
            *(float2*)&g_S[0][ui] = st;
        }
    }
    gridbar(1u);

    for (int t = 1; t < Tt; ++t) {
        const float* Sp = g_S[(t + 1) & 1];

        ull acc[2][4];
        #pragma unroll
        for (int i = 0; i < 2; ++i)
            #pragma unroll
            for (int j = 0; j < 4; ++j) acc[i][j] = 0ull;

        #pragma unroll 4
        for (int k = k0; k < k0 + 128; ++k) {
            float2 s = __ldcg((const float2*)&Sp[(size_t)k * Bb + 2 * lane]);
            ull s0 = pk2(s.x, s.x);
            ull s1 = pk2(s.y, s.y);
            ulonglong2 wA = *(const ulonglong2*)&Ws[k * 8];
            ulonglong2 wB = *(const ulonglong2*)&Ws[k * 8 + 4];
            acc[0][0] = ffma2(s0, wA.x, acc[0][0]);
            acc[0][1] = ffma2(s0, wA.y, acc[0][1]);
            acc[0][2] = ffma2(s0, wB.x, acc[0][2]);
            acc[0][3] = ffma2(s0, wB.y, acc[0][3]);
            acc[1][0] = ffma2(s1, wA.x, acc[1][0]);
            acc[1][1] = ffma2(s1, wA.y, acc[1][1]);
            acc[1][2] = ffma2(s1, wB.x, acc[1][2]);
            acc[1][3] = ffma2(s1, wB.y, acc[1][3]);
        }

        // red2[w][j*64 + b], b = 2*lane (+1): one STS.128 per n-pair
        #pragma unroll
        for (int j = 0; j < 4; ++j) {
            ulonglong2 v; v.x = acc[0][j]; v.y = acc[1][j];
            *(ulonglong2*)&red2[w][j * 64 + 2 * lane] = v;
        }
        __syncthreads();

        if (tid < 128) {
            int p = tid >> 5, m = tid & 31;             // npair p, b-pair 2m
            ull sb0 = 0ull, sb1 = 0ull;                 // packed along n, per b
            #pragma unroll
            for (int ww = 0; ww < 8; ++ww) {
                ulonglong2 v = *(const ulonglong2*)&red2[ww][p * 64 + 2 * m];
                sb0 = addf2(sb0, v.x);
                sb1 = addf2(sb1, v.y);
            }
            float2 pre0 = upk2(sb0);                    // (h0,h1) for b=2m
            float2 pre1 = upk2(sb1);                    // (h0,h1) for b=2m+1
            int h0i = n0 + 2 * p;
            size_t u0 = ((size_t)t * Hh + h0i) * Bb + 2 * m;
            size_t u1 = u0 + Bb;                        // h0i+1
            float2 uh0 = *(const float2*)&g_U[u0];
            float2 uh1 = *(const float2*)&g_U[u1];
            float2 st0 = make_float2(ftanh(pre0.x + uh0.x), ftanh(pre1.x + uh0.y));
            float2 st1 = make_float2(ftanh(pre0.y + uh1.x), ftanh(pre1.y + uh1.y));
            *(float2*)&g_U[u0] = st0;
            *(float2*)&g_U[u1] = st1;
            float* Sn = g_S[t & 1];
            *(float2*)&Sn[(size_t)h0i * Bb + 2 * m] = st0;
            *(float2*)&Sn[(size_t)(h0i + 1) * Bb + 2 * m] = st1;
        }
        gridbar((unsigned)((t & 1) ^ 1));
    }
}

// out[b][t][o] = bout[o] + sum_h st[t][h][b] * Wout[h][o]
// A = st_t[h][b] (b contig) -> direct smem [k][b]. B = Wout (o contig) -> direct.
__global__ __launch_bounds__(256) void out_gemm_kernel(const float* __restrict__ Wout,
                                                       const float* __restrict__ bout,
                                                       float* __restrict__ out) {
    const int t  = blockIdx.y;
    const int o0 = blockIdx.x * 64;
    __shared__ __align__(16) float As[16][68];   // [k][b]
    __shared__ __align__(16) float Bs[16][68];   // [k][o]
    const int tid = threadIdx.x;
    const int tx = tid & 15, ty = tid >> 4;      // tx -> o (4), ty -> b (4)
    const int r = tid >> 4, c = (tid & 15) * 4;

    ull acc[4][2];
    #pragma unroll
    for (int i = 0; i < 4; ++i) { acc[i][0] = 0ull; acc[i][1] = 0ull; }

    float4 ra = *(const float4*)&g_U[((size_t)t * Hh + r) * Bb + c];
    float4 rb = *(const float4*)(Wout + (size_t)r * Oo + o0 + c);

    for (int k0 = 0; k0 < Hh; k0 += 16) {
        *(float4*)&As[r][c] = ra;
        *(float4*)&Bs[r][c] = rb;
        __syncthreads();
        if (k0 + 16 < Hh) {
            ra = *(const float4*)&g_U[((size_t)t * Hh + k0 + 16 + r) * Bb + c];
            rb = *(const float4*)(Wout + (size_t)(k0 + 16 + r) * Oo + o0 + c);
        }
        #pragma unroll
        for (int kk = 0; kk < 16; ++kk) {
            float4 a = *(const float4*)&As[kk][4 * ty];
            ulonglong2 b2 = *(const ulonglong2*)&Bs[kk][4 * tx];
            float av[4] = {a.x, a.y, a.z, a.w};
            #pragma unroll
            for (int i = 0; i < 4; ++i) {
                ull sp = pk2(av[i], av[i]);
                acc[i][0] = ffma2(sp, b2.x, acc[i][0]);
                acc[i][1] = ffma2(sp, b2.y, acc[i][1]);
            }
        }
        __syncthreads();
    }
    float4 bo = *(const float4*)(bout + o0 + 4 * tx);
    #pragma unroll
    for (int i = 0; i < 4; ++i) {
        float2 lo = upk2(acc[i][0]), hi = upk2(acc[i][1]);
        float4 v = make_float4(lo.x + bo.x, lo.y + bo.y, hi.x + bo.z, hi.y + bo.w);
        int b = 4 * ty + i;
        *(float4*)&out[((size_t)b * Tt + t) * Oo + o0 + 4 * tx] = v;
    }
}

extern "C" void kernel_launch(void* const* d_in, const int* in_sizes, int n_in,
                              void* d_out, int out_size) {
    const float* x    = (const float*)d_in[0];
    const float* Wx   = (const float*)d_in[1];
    const float* Wh   = (const float*)d_in[2];
    const float* bias = (const float*)d_in[3];
    const float* Wout = (const float*)d_in[4];
    const float* bout = (const float*)d_in[5];
    float* out = (float*)d_out;

    transpose_x_kernel<<<dim3(Tt / 32, Ff / 32, Bb), dim3(32, 8)>>>(x);
    u_gemm_kernel     <<<dim3(Hh / 64, Tt), 256>>>(Wx, bias);
    rnn_kernel        <<<RNCTA, 256>>>(Wh);
    out_gemm_kernel   <<<dim3(Oo / 64, Tt), 256>>>(Wout, bout, out);
}